// round 2
// baseline (speedup 1.0000x reference)
#include <cuda_runtime.h>
#include <math.h>

#define NY 1024
#define NX 1024
#define NSTEPS 64
#define NPTS (NY*NX)

__device__ float g_H[NPTS];
__device__ float g_Z0[NPTS];
__device__ float g_Z1[NPTS];
__device__ float g_smb[NPTS];
__device__ float g_D[NPTS];               // NX-padded: D(j,i) at j*NX+i, valid i,j < 1023
__device__ int g_maxDbits[NSTEPS];
__device__ unsigned g_arrive = 0;
__device__ volatile unsigned g_epoch = 0;

__device__ __forceinline__ float smb_of(float Zs, float precip, float mask,
                                        float tma_low, float tmj_low) {
    const float LAPSE = 0.0065f;
    const float MELTF = 0.5f;
    float T_ma = tma_low - LAPSE * Zs;
    float T_mj = tmj_low - LAPSE * Zs;
    float acc = precip * (T_ma < 0.0f ? 1.0f : 0.0f);
    float abl = MELTF * fmaxf(T_mj, 0.0f);
    return (acc - abl) * mask;
}

// Software grid barrier. Co-residency of all nb blocks is guaranteed by the
// host-side occupancy computation. Writer-side __threadfence orders stores to
// L2 (release); reader-side __threadfence emits CCTL.IVALL which invalidates
// this SM's L1D, so post-barrier loads refetch peer data from L2 (acquire).
__device__ __forceinline__ void gridbar(unsigned nb) {
    __syncthreads();
    if (threadIdx.x == 0) {
        unsigned e = g_epoch;
        __threadfence();
        if (atomicAdd(&g_arrive, 1u) == nb - 1u) {
            g_arrive = 0;            // safe: all others already incremented, now spinning
            __threadfence();
            g_epoch = e + 1u;
        } else {
            while (g_epoch == e) __nanosleep(32);
        }
        __threadfence();
    }
    __syncthreads();
}

__global__ void __launch_bounds__(256)
k_persist(const float* __restrict__ precip,
          const float* __restrict__ tma_p,
          const float* __restrict__ tmj_p,
          const float* __restrict__ Ztopo,
          const float* __restrict__ mask,
          float* __restrict__ out,
          int nb) {
    const int tid = threadIdx.x;
    const int gthreads = nb * 256;
    const int gtid = blockIdx.x * 256 + tid;
    const float tma = tma_p[0];
    const float tmj = tmj_p[0];

    // ---- init phase ----
    for (int idx = gtid; idx < NPTS; idx += gthreads) {
        float zt = Ztopo[idx];
        g_H[idx]   = 0.0f;
        g_Z0[idx]  = zt;
        g_smb[idx] = smb_of(zt, precip[idx], mask[idx], tma, tmj);
    }
    if (gtid < NSTEPS) g_maxDbits[gtid] = 0;
    gridbar(nb);

    float time = 0.0f, tlast = 0.0f;

    const double RG = 910.0 * 9.81;
    const float CFACT = (float)(1e-17 * RG * RG * RG);

    for (int s = 0; s < NSTEPS; s++) {
        const float* zread  = (s & 1) ? g_Z1 : g_Z0;
        float*       zwrite = (s & 1) ? g_Z0 : g_Z1;

        // ---- pass 1: staggered D field + global max ----
        float local = 0.0f;
        for (int lin = gtid; lin < (NY - 1) * NX; lin += gthreads) {
            int i = lin & (NX - 1);
            if (i == NX - 1) continue;
            float h00 = g_H[lin],      h01 = g_H[lin + 1];
            float h10 = g_H[lin + NX], h11 = g_H[lin + NX + 1];
            float z00 = zread[lin],      z01 = zread[lin + 1];
            float z10 = zread[lin + NX], z11 = zread[lin + NX + 1];

            float H_avg = 0.25f * (h00 + h11 + h01 + h10);
            float sx = 0.5f * ((z01 - z00) / 50.0f + (z11 - z10) / 50.0f);
            float sy = 0.5f * ((z10 - z00) / 50.0f + (z11 - z01) / 50.0f);
            float snorm = sqrtf(sx * sx + sy * sy + 1e-10f);

            float h2 = H_avg * H_avg;
            float h5 = h2 * h2 * H_avg;
            float D = CFACT * h5 * (snorm * snorm) + 1e-10f;
            g_D[lin] = D;
            local = fmaxf(local, D);
        }
        // block-level max reduce -> one atomic per block
        #pragma unroll
        for (int o = 16; o > 0; o >>= 1)
            local = fmaxf(local, __shfl_xor_sync(0xFFFFFFFFu, local, o));
        __shared__ float wmax[8];
        int lane = tid & 31, wid = tid >> 5;
        if (lane == 0) wmax[wid] = local;
        __syncthreads();
        if (tid == 0) {
            float m = wmax[0];
            #pragma unroll
            for (int w = 1; w < 8; w++) m = fmaxf(m, wmax[w]);
            atomicMax(&g_maxDbits[s], __float_as_int(m));
        }
        gridbar(nb);

        // ---- dt from global max (identical in every thread) ----
        float maxD = __int_as_float(g_maxDbits[s]);
        float dt = fminf(2500.0f / (2.7f * maxD), 0.5f);
        if (!(time < 32.0f)) dt = 0.0f;
        float tnew = time + dt;
        bool  upd  = (tnew - tlast) >= 5.0f;

        const int last = (s == NSTEPS - 1);

        // ---- pass 2: flux divergence + H/Z update (+ conditional SMB) ----
        for (int idx = gtid; idx < NPTS; idx += gthreads) {
            int i = idx & (NX - 1);
            int j = idx >> 10;
            float H  = g_H[idx];
            float Hn = H;
            if (i > 0 && i < NX - 1 && j > 0 && j < NY - 1) {
                int di = idx - NX - 1;                 // (j-1, i-1) in NX-padded D
                float Dmm = g_D[di],      Dm0 = g_D[di + 1];
                float D0m = g_D[di + NX], D00 = g_D[di + NX + 1];

                float zc = zread[idx];
                float zl = zread[idx - 1],  zr = zread[idx + 1];
                float zu = zread[idx - NX], zd = zread[idx + NX];

                float qxr = -(0.5f * (Dm0 + D00)) * (zr - zc) / 50.0f;
                float qxl = -(0.5f * (Dmm + D0m)) * (zc - zl) / 50.0f;
                float qyd = -(0.5f * (D0m + D00)) * (zd - zc) / 50.0f;
                float qyu = -(0.5f * (Dmm + Dm0)) * (zc - zu) / 50.0f;
                float dHdt = -((qxr - qxl) / 50.0f + (qyd - qyu) / 50.0f);
                Hn = H + dt * (dHdt + g_smb[idx]);
            }
            Hn = fmaxf(Hn, 0.0f);
            float Zn = Ztopo[idx] + Hn;
            g_H[idx]    = Hn;
            zwrite[idx] = Zn;
            if (upd)
                g_smb[idx] = smb_of(Zn, precip[idx], mask[idx], tma, tmj);
            if (last) out[idx] = Hn;
        }
        time = tnew;
        if (upd) tlast = tnew;
        gridbar(nb);
    }
}

extern "C" void kernel_launch(void* const* d_in, const int* in_sizes, int n_in,
                              void* d_out, int out_size) {
    const float* precip = (const float*)d_in[0];
    const float* tma_p  = (const float*)d_in[1];
    const float* tmj_p  = (const float*)d_in[2];
    const float* Ztopo  = (const float*)d_in[3];
    const float* mask   = (const float*)d_in[4];
    float* out = (float*)d_out;

    int dev = 0;
    cudaGetDevice(&dev);
    int sms = 0;
    cudaDeviceGetAttribute(&sms, cudaDevAttrMultiProcessorCount, dev);
    int maxb = 0;
    cudaOccupancyMaxActiveBlocksPerMultiprocessor(&maxb, k_persist, 256, 0);
    if (maxb < 1) maxb = 1;
    long long nb = (long long)sms * maxb;
    if (nb > 4096) nb = 4096;
    if (nb < 1) nb = 1;

    k_persist<<<(int)nb, 256>>>(precip, tma_p, tmj_p, Ztopo, mask, out, (int)nb);
}

// round 3
// speedup vs baseline: 1.0559x; 1.0559x over previous
#include <cuda_runtime.h>
#include <math.h>

#define NY 1024
#define NX 1024
#define NSTEPS 64
#define NPTS (NY*NX)

__device__ float g_H0[NPTS];
__device__ float g_H1[NPTS];
__device__ float g_smb[NPTS];
__device__ float g_D[NPTS];            // NX-padded: D(j,i) at j*NX+i, valid j<1023,i<1023
__device__ int g_maxDbits[NSTEPS];
__device__ unsigned g_arrive;

// ---- fence-free gpu-scope acquire/release primitives (no CCTL.IVALL) ----
static __device__ __forceinline__ unsigned ld_acq(const unsigned* p) {
    unsigned v;
    asm volatile("ld.acquire.gpu.global.u32 %0, [%1];" : "=r"(v) : "l"(p) : "memory");
    return v;
}
static __device__ __forceinline__ void red_add_rel(unsigned* p, unsigned v) {
    asm volatile("red.release.gpu.global.add.u32 [%0], %1;" :: "l"(p), "r"(v) : "memory");
}

// Monotonic counting grid barrier: every block adds 1 (release), spins until
// counter >= target (acquire). No reset within a run; host-side reset kernel
// zeroes it before each replay. Skew is bounded to one barrier (counter can
// only reach k*nb after every block has made its k-th arrival).
static __device__ __forceinline__ void gridbar(unsigned target) {
    __syncthreads();
    if (threadIdx.x == 0) {
        red_add_rel(&g_arrive, 1u);
        while (ld_acq(&g_arrive) < target) __nanosleep(32);
    }
    __syncthreads();
}

static __device__ __forceinline__ float ldf(const float* p, bool cg) {
    return cg ? __ldcg(p) : *p;
}
static __device__ __forceinline__ void stf(float* p, float v, bool cg) {
    if (cg) __stcg(p, v); else *p = v;
}

static __device__ __forceinline__ float smb_of(float Zs, float precip, float mask,
                                               float tma_low, float tmj_low) {
    const float LAPSE = 0.0065f;
    const float MELTF = 0.5f;
    float T_ma = tma_low - LAPSE * Zs;
    float T_mj = tmj_low - LAPSE * Zs;
    float acc = precip * (T_ma < 0.0f ? 1.0f : 0.0f);
    float abl = MELTF * fmaxf(T_mj, 0.0f);
    return (acc - abl) * mask;
}

__global__ void k_reset() {
    if (threadIdx.x == 0) g_arrive = 0u;
    if (threadIdx.x < NSTEPS) g_maxDbits[threadIdx.x] = 0;
}

__global__ void __launch_bounds__(1024, 1)
k_persist(const float* __restrict__ precip,
          const float* __restrict__ tma_p,
          const float* __restrict__ tmj_p,
          const float* __restrict__ Ztopo,
          const float* __restrict__ mask,
          float* __restrict__ out) {
    const int tid = threadIdx.x;           // column index
    const int nb  = gridDim.x;
    const int bid = blockIdx.x;
    const int lane = tid & 31, wid = tid >> 5;

    // contiguous row band [r0, r1) owned by this block
    int base = NY / nb, rem = NY % nb;
    int r0 = bid * base + (bid < rem ? bid : rem);
    int r1 = r0 + base + (bid < rem ? 1 : 0);

    const float tma = tma_p[0], tmj = tmj_p[0];
    const double RG = 910.0 * 9.81;
    const float CFACT = (float)(1e-17 * RG * RG * RG);

    __shared__ float wmax[32];

    // ---- init own rows (stores don't allocate L1; stcg keeps halo model clean)
    for (int j = r0; j < r1; j++) {
        int idx = j * NX + tid;
        __stcg(&g_H0[idx], 0.0f);
        float zt = Ztopo[idx];
        g_smb[idx] = smb_of(zt, precip[idx], mask[idx], tma, tmj);
    }
    unsigned target = nb;
    gridbar(target); target += nb;

    float time = 0.0f, tlast = 0.0f;

    for (int s = 0; s < NSTEPS; s++) {
        const float* Hr = (s & 1) ? g_H1 : g_H0;
        float*       Hw = (s & 1) ? g_H0 : g_H1;

        // ---- pass 1: D rows [dj0, dj1) (boundary D row recomputed by both neighbors)
        int dj0 = (r0 > 0) ? r0 - 1 : 0;
        int dj1 = (r1 < NY) ? r1 : NY - 1;
        float lmax = 0.0f;
        if (tid < NX - 1) {
            for (int j = dj0; j < dj1; j++) {
                bool cgj  = (j     <= r0) || (j     >= r1 - 1);
                bool cgj1 = (j + 1 <= r0) || (j + 1 >= r1 - 1);
                int idx = j * NX + tid;
                float h00 = ldf(&Hr[idx],          cgj);
                float h01 = ldf(&Hr[idx + 1],      cgj);
                float h10 = ldf(&Hr[idx + NX],     cgj1);
                float h11 = ldf(&Hr[idx + NX + 1], cgj1);
                float z00 = Ztopo[idx]          + h00;
                float z01 = Ztopo[idx + 1]      + h01;
                float z10 = Ztopo[idx + NX]     + h10;
                float z11 = Ztopo[idx + NX + 1] + h11;

                float H_avg = 0.25f * (h00 + h11 + h01 + h10);
                float sx = 0.5f * ((z01 - z00) / 50.0f + (z11 - z10) / 50.0f);
                float sy = 0.5f * ((z10 - z00) / 50.0f + (z11 - z01) / 50.0f);
                float sn = sqrtf(sx * sx + sy * sy + 1e-10f);

                float h2 = H_avg * H_avg;
                float h5 = h2 * h2 * H_avg;
                float D = CFACT * h5 * (sn * sn) + 1e-10f;
                g_D[idx] = D;
                lmax = fmaxf(lmax, D);
            }
        }
        // block max -> one atomic
        #pragma unroll
        for (int o = 16; o > 0; o >>= 1)
            lmax = fmaxf(lmax, __shfl_xor_sync(0xFFFFFFFFu, lmax, o));
        if (lane == 0) wmax[wid] = lmax;
        __syncthreads();
        if (wid == 0) {
            float m = wmax[lane];
            #pragma unroll
            for (int o = 16; o > 0; o >>= 1)
                m = fmaxf(m, __shfl_xor_sync(0xFFFFFFFFu, m, o));
            if (lane == 0) atomicMax(&g_maxDbits[s], __float_as_int(m));
        }
        gridbar(target); target += nb;

        // ---- dt (identical in every thread)
        float maxD = __int_as_float(__ldcg(&g_maxDbits[s]));
        float dt = fminf(2500.0f / (2.7f * maxD), 0.5f);
        if (!(time < 32.0f)) dt = 0.0f;
        float tnew = time + dt;
        bool  upd  = (tnew - tlast) >= 5.0f;
        const int last = (s == NSTEPS - 1);

        // ---- pass 2: flux divergence + H update (+ conditional SMB, final out)
        for (int j = r0; j < r1; j++) {
            bool cgj = (j     <= r0) || (j     >= r1 - 1);
            bool cgm = (j - 1 <= r0) || (j - 1 >= r1 - 1);
            bool cgp = (j + 1 <= r0) || (j + 1 >= r1 - 1);
            int idx = j * NX + tid;
            float H  = ldf(&Hr[idx], cgj);
            float Hn = H;
            if (tid > 0 && tid < NX - 1 && j > 0 && j < NY - 1) {
                int di = idx - NX - 1;
                float Dmm = g_D[di],      Dm0 = g_D[di + 1];
                float D0m = g_D[di + NX], D00 = g_D[di + NX + 1];

                float zc = Ztopo[idx]      + H;
                float zl = Ztopo[idx - 1]  + ldf(&Hr[idx - 1],  cgj);
                float zr = Ztopo[idx + 1]  + ldf(&Hr[idx + 1],  cgj);
                float zu = Ztopo[idx - NX] + ldf(&Hr[idx - NX], cgm);
                float zd = Ztopo[idx + NX] + ldf(&Hr[idx + NX], cgp);

                float qxr = -(0.5f * (Dm0 + D00)) * (zr - zc) / 50.0f;
                float qxl = -(0.5f * (Dmm + D0m)) * (zc - zl) / 50.0f;
                float qyd = -(0.5f * (D0m + D00)) * (zd - zc) / 50.0f;
                float qyu = -(0.5f * (Dmm + Dm0)) * (zc - zu) / 50.0f;
                float dHdt = -((qxr - qxl) / 50.0f + (qyd - qyu) / 50.0f);
                Hn = H + dt * (dHdt + g_smb[idx]);
            }
            Hn = fmaxf(Hn, 0.0f);
            stf(&Hw[idx], Hn, cgj);
            if (upd) {
                float Zn = Ztopo[idx] + Hn;
                g_smb[idx] = smb_of(Zn, precip[idx], mask[idx], tma, tmj);
            }
            if (last) out[idx] = Hn;
        }
        time = tnew;
        if (upd) tlast = tnew;
        gridbar(target); target += nb;
    }
}

extern "C" void kernel_launch(void* const* d_in, const int* in_sizes, int n_in,
                              void* d_out, int out_size) {
    const float* precip = (const float*)d_in[0];
    const float* tma_p  = (const float*)d_in[1];
    const float* tmj_p  = (const float*)d_in[2];
    const float* Ztopo  = (const float*)d_in[3];
    const float* mask   = (const float*)d_in[4];
    float* out = (float*)d_out;

    int dev = 0;
    cudaGetDevice(&dev);
    int sms = 0;
    cudaDeviceGetAttribute(&sms, cudaDevAttrMultiProcessorCount, dev);
    if (sms < 1) sms = 1;
    if (sms > NY) sms = NY;

    k_reset<<<1, 64>>>();
    k_persist<<<sms, 1024>>>(precip, tma_p, tmj_p, Ztopo, mask, out);
}